// round 11
// baseline (speedup 1.0000x reference)
#include <cuda_runtime.h>
#include <cstdint>
#include <math.h>

#define BB 4
#define CIN 256
#define PP 64
#define HH 128
#define WW 128
#define HWSZ (HH*WW)
#define KK 8
#define BN_EPS 1e-5f
#define NCTA234 (4*16*BB)

// Scratch (device globals: allocation-free)
__device__ float g_h[BB*PP*HWSZ];      // after 1x1 conv + BN + SiLU
__device__ float g_mind[BB*HWSZ];      // per-pixel min distance / (tau+1e-6)
__device__ unsigned int g_minbits[BB];
__device__ unsigned int g_maxbits[BB];
__device__ unsigned int g_bar;

__device__ __forceinline__ float sigmoidf_(float x){ return 1.0f/(1.0f+__expf(-x)); }
__device__ __forceinline__ float siluf_(float x){ return x*sigmoidf_(x); }

__device__ __forceinline__ uint32_t smem_u32(const void* p){
    uint32_t a;
    asm("{ .reg .u64 t; cvta.to.shared.u64 t, %1; cvt.u32.u64 %0, t; }" : "=r"(a) : "l"(p));
    return a;
}
__device__ __forceinline__ uint32_t pack_bf16x2(float x0, float x1){
    uint32_t r;
    asm("cvt.rn.bf16x2.f32 %0, %1, %2;" : "=r"(r) : "f"(x1), "f"(x0));
    return r;
}
__device__ __forceinline__ void ldsm_x4(uint32_t* r, uint32_t addr){
    asm volatile("ldmatrix.sync.aligned.m8n8.x4.shared.b16 {%0,%1,%2,%3}, [%4];"
        : "=r"(r[0]),"=r"(r[1]),"=r"(r[2]),"=r"(r[3]) : "r"(addr));
}
__device__ __forceinline__ void ldsm_x2(uint32_t& r0, uint32_t& r1, uint32_t addr){
    asm volatile("ldmatrix.sync.aligned.m8n8.x2.shared.b16 {%0,%1}, [%2];"
        : "=r"(r0),"=r"(r1) : "r"(addr));
}
__device__ __forceinline__ void mma_bf16(float* d, const uint32_t* a, uint32_t b0, uint32_t b1){
    asm volatile("mma.sync.aligned.m16n8k16.row.col.f32.bf16.bf16.f32 "
        "{%0,%1,%2,%3},{%4,%5,%6,%7},{%8,%9},{%0,%1,%2,%3};"
        : "+f"(d[0]),"+f"(d[1]),"+f"(d[2]),"+f"(d[3])
        : "r"(a[0]),"r"(a[1]),"r"(a[2]),"r"(a[3]),"r"(b0),"r"(b1));
}
__device__ __forceinline__ uint32_t ldcg_u32(const unsigned int* p){
    uint32_t v;
    asm volatile("ld.global.cg.u32 %0, [%1];" : "=r"(v) : "l"(p));
    return v;
}
__device__ __forceinline__ void bar_arrive_release(unsigned int* p){
    uint32_t old;
    asm volatile("atom.global.release.gpu.add.u32 %0, [%1], 1;" : "=r"(old) : "l"(p) : "memory");
}
__device__ __forceinline__ uint32_t ld_acquire(const unsigned int* p){
    uint32_t v;
    asm volatile("ld.global.acquire.gpu.u32 %0, [%1];" : "=r"(v) : "l"(p) : "memory");
    return v;
}

// ---------------- k1 SMEM layout ----------------
#define APITCH 36                          // u32 pitch for A (144B)
#define BPITCH 132                         // u32 pitch for B (528B), full K
#define SM_SC    0
#define SM_SH    256
#define ABYTES   (128*APITCH*4)            // 18432
#define SM_A0    512
#define SM_B     (SM_A0 + 2*ABYTES)        // 37376
#define SM_TOTAL (SM_B + 64*BPITCH*4)      // 71168

// stage 32 x-floats (one K=64 chunk of A) into registers
static __device__ __forceinline__ void a_stage(const float* __restrict__ xp,
                                               int kn, float* xa, int tid){
    int kg0 = tid >> 7;                    // 0 or 1
    #pragma unroll
    for (int it = 0; it < 4; it++){
        int kbase = kn*64 + (kg0 + it*2)*8;
        #pragma unroll
        for (int t = 0; t < 4; t++){
            xa[it*8 + 2*t]     = xp[(size_t)(kbase + 2*t    )*HWSZ];
            xa[it*8 + 2*t + 1] = xp[(size_t)(kbase + 2*t + 1)*HWSZ];
        }
    }
}
// cvt staged regs -> bf16x2, STS.128 into buffer
static __device__ __forceinline__ void a_commit(const float* xa, uint32_t* a_buf, int tid){
    int px  = tid & 127;
    int kg0 = tid >> 7;
    #pragma unroll
    for (int it = 0; it < 4; it++){
        int kg = kg0 + it*2;
        uint32_t hi[4];
        #pragma unroll
        for (int t = 0; t < 4; t++)
            hi[t] = pack_bf16x2(xa[it*8 + 2*t], xa[it*8 + 2*t + 1]);
        *(uint4*)(a_buf + px*APITCH + kg*4) = make_uint4(hi[0],hi[1],hi[2],hi[3]);
    }
}

// ---------------------------------------------------------------- k1: 1x1 conv, bf16 HMMA
// 2 pixel-blocks per CTA, B converted once (full K), register-staged A pipeline.
__global__ __launch_bounds__(256, 2)
void k1_mma(const float* __restrict__ x, const float* __restrict__ w,
            const float* __restrict__ bn){
    extern __shared__ char smem[];
    uint32_t sb = smem_u32(smem);
    float* ssc = (float*)(smem + SM_SC);
    float* ssh = (float*)(smem + SM_SH);
    uint32_t* b_buf = (uint32_t*)(smem + SM_B);

    int b    = blockIdx.y;
    int pix0 = blockIdx.x * 256;
    int tid  = threadIdx.x;
    int wid  = tid >> 5;
    int lane = tid & 31;
    int gid  = lane >> 2, tig = lane & 3;
    int pw   = (wid >> 1) * 32;
    int n0w  = (wid & 1) * 32;

    if (blockIdx.x == 0 && blockIdx.y == 0 && tid < BB + 1){
        if (tid < BB){ g_minbits[tid] = 0x7F7FFFFFu; g_maxbits[tid] = 0u; }
        else g_bar = 0u;
    }
    if (tid < PP){
        float g = bn[tid], be = bn[PP+tid], m = bn[2*PP+tid], v = bn[3*PP+tid];
        float sc = g * rsqrtf(v + BN_EPS);
        ssc[tid] = sc; ssh[tid] = be - m*sc;
    }

    // ---- convert B once: 64 couts x 256 K -> bf16x2 [co][kpair], pitch 132 u32 ----
    {
        int co = tid & 63;
        int kq = (tid >> 6) * 64;            // k-float base: 0,64,128,192
        const float* wp = w + co*CIN + kq;
        #pragma unroll
        for (int t = 0; t < 8; t++){
            float4 w0 = *(const float4*)(wp + t*8);
            float4 w1 = *(const float4*)(wp + t*8 + 4);
            uint32_t hi[4];
            hi[0] = pack_bf16x2(w0.x, w0.y);
            hi[1] = pack_bf16x2(w0.z, w0.w);
            hi[2] = pack_bf16x2(w1.x, w1.y);
            hi[3] = pack_bf16x2(w1.z, w1.w);
            *(uint4*)(b_buf + co*BPITCH + kq/2 + t*4) = make_uint4(hi[0],hi[1],hi[2],hi[3]);
        }
    }

    uint32_t a_row = (uint32_t)(lane & 15);
    uint32_t a_kof = (uint32_t)(lane >> 4) * 16;
    uint32_t b_row = (uint32_t)(lane & 7);
    uint32_t b_kof = (uint32_t)((lane >> 3) & 1) * 16;

    float xa[32];

    #pragma unroll 1
    for (int pb = 0; pb < 2; pb++){
        const float* xp = x + (size_t)b*CIN*HWSZ + pix0 + pb*128 + (tid & 127);

        float acc[2][4][4];
        #pragma unroll
        for (int mt=0;mt<2;mt++)
            #pragma unroll
            for (int j=0;j<4;j++)
                #pragma unroll
                for (int i=0;i<4;i++) acc[mt][j][i] = 0.f;

        // prologue: chunk 0 (stalls once; also covers B-convert visibility via sync)
        a_stage(xp, 0, xa, tid);
        a_commit(xa, (uint32_t*)(smem + SM_A0), tid);
        __syncthreads();

        #pragma unroll 1
        for (int c = 0; c < 4; c++){
            uint32_t curA = sb + SM_A0 + (uint32_t)(c & 1) * ABYTES;
            // 1) issue next chunk's loads (independent -> in flight during MMA)
            if (c < 3) a_stage(xp, c+1, xa, tid);
            // 2) MMA on current buffer: 4 k16 steps
            #pragma unroll
            for (int ks = 0; ks < 4; ks++){
                uint32_t kbyteA = (uint32_t)ks * 32;
                uint32_t kbyteB = (uint32_t)c * 128 + (uint32_t)ks * 32;
                uint32_t ah[2][4];
                #pragma unroll
                for (int mt=0;mt<2;mt++){
                    uint32_t ra = (pw + mt*16 + a_row) * (APITCH*4) + kbyteA + a_kof;
                    ldsm_x4(ah[mt], curA + ra);
                }
                #pragma unroll
                for (int j=0;j<4;j++){
                    uint32_t rb = (n0w + j*8 + b_row) * (BPITCH*4) + kbyteB + b_kof;
                    uint32_t bh0, bh1;
                    ldsm_x2(bh0, bh1, sb + SM_B + rb);
                    #pragma unroll
                    for (int mt=0;mt<2;mt++)
                        mma_bf16(acc[mt][j], ah[mt], bh0, bh1);
                }
            }
            // 3) now consume the staged loads (latency already hidden by MMA)
            if (c < 3) a_commit(xa, (uint32_t*)(smem + SM_A0 + ((c+1) & 1) * ABYTES), tid);
            __syncthreads();
        }

        // epilogue: BN + SiLU, store
        #pragma unroll
        for (int mt=0;mt<2;mt++){
            int pix = pix0 + pb*128 + pw + mt*16 + gid;
            #pragma unroll
            for (int j=0;j<4;j++){
                int cc = n0w + j*8 + tig*2;
                float sc0 = ssc[cc],   sh0 = ssh[cc];
                float sc1 = ssc[cc+1], sh1 = ssh[cc+1];
                float* h0 = g_h + (size_t)(b*PP + cc)*HWSZ;
                float* h1 = h0 + HWSZ;
                h0[pix]   = siluf_(fmaf(acc[mt][j][0], sc0, sh0));
                h1[pix]   = siluf_(fmaf(acc[mt][j][1], sc1, sh1));
                h0[pix+8] = siluf_(fmaf(acc[mt][j][2], sc0, sh0));
                h1[pix+8] = siluf_(fmaf(acc[mt][j][3], sc1, sh1));
            }
        }
    }
}

// ---------------- k234 dynamic smem layout (float offsets) ----------------
#define K234_FLOATS 23440
#define K234_SMEM   (K234_FLOATS*4)

// ---------------------------------------------------------------- k234: dw3x3+dist -> barrier -> attention -> fused apply
__global__ __launch_bounds__(256) void k234(
        const float* __restrict__ dw, const float* __restrict__ bn,
        const float* __restrict__ protos,
        const float* __restrict__ bs_dw, const float* __restrict__ bs_bn1,
        const float* __restrict__ bs_pw, const float* __restrict__ bs_bn2,
        const float* __restrict__ bl_dw, const float* __restrict__ bl_bn1,
        const float* __restrict__ bl_pw, const float* __restrict__ bl_bn2,
        const float* __restrict__ fuse_w, const float* __restrict__ fuse_b,
        const float* __restrict__ gamma,
        const float* __restrict__ x, float* __restrict__ out){
    extern __shared__ float sm[];
    float* tile = sm;                 // [c][r][col] = c*340 + r*34 + col
    float* ps   = sm + 21760;         // [k][c]
    float* sdw  = sm + 22272;         // [c][j]
    float* ssc  = sm + 22848;
    float* ssh  = sm + 22912;
    float* pn   = sm + 22976;
    float* smin = sm + 22984;
    float* smax = sm + 22992;
    float* sdev = sm + 23000;         // [ly][lx] = ly*36 + lx
    float* sminmax = sm + 23432;

    int b   = blockIdx.z;
    int gx0 = blockIdx.x*32, gy0 = blockIdx.y*8;
    int tx  = threadIdx.x,  ty  = threadIdx.y;
    int tid = ty*32 + tx;

    for (int i = tid; i < KK*PP; i += 256) ps[i] = protos[i];
    for (int i = tid; i < PP*9;  i += 256) sdw[i] = dw[i];
    if (tid < PP){
        float g=bn[tid], be=bn[PP+tid], m=bn[2*PP+tid], v=bn[3*PP+tid];
        float sc = g*rsqrtf(v+BN_EPS);
        ssc[tid] = sc; ssh[tid] = be - m*sc;
    }
    if (tid < KK){
        float s = 0.f;
        #pragma unroll
        for (int c=0;c<PP;c++){ float p = protos[tid*PP+c]; s = fmaf(p,p,s); }
        pn[tid] = s;
    }

    // ---- single-pass halo tile load: all 64 channels ----
    const float* hb = g_h + (size_t)b*PP*HWSZ;
    for (int i = tid; i < 64*340; i += 256){
        int c   = i / 340;
        int rem = i - c*340;
        int r   = rem / 34;
        int col = rem - r*34;
        int yy = gy0 - 1 + r, xx = gx0 - 1 + col;
        float v = 0.f;
        if ((unsigned)yy < HH && (unsigned)xx < WW)
            v = hb[(size_t)c*HWSZ + yy*WW + xx];
        tile[i] = v;
    }
    __syncthreads();

    float nf = 0.f, dot[KK];
    #pragma unroll
    for (int k=0;k<KK;k++) dot[k] = 0.f;

    #pragma unroll 4
    for (int c = 0; c < PP; c++){
        const float* tc = tile + c*340 + ty*34 + tx;
        float s = 0.f;
        #pragma unroll
        for (int dy=0;dy<3;dy++)
            #pragma unroll
            for (int dx=0;dx<3;dx++)
                s = fmaf(sdw[c*9+dy*3+dx], tc[dy*34+dx], s);
        float pr = siluf_(fmaf(s, ssc[c], ssh[c]));
        nf = fmaf(pr, pr, nf);
        #pragma unroll
        for (int k=0;k<KK;k++) dot[k] = fmaf(pr, ps[k*PP+c], dot[k]);
    }

    float m = 3.4e38f;
    #pragma unroll
    for (int k=0;k<KK;k++) m = fminf(m, nf + pn[k] - 2.f*dot[k]);
    float md = sqrtf(fmaxf(m, 0.f)) * (1.0f/(1.0f + 1e-6f));
    g_mind[b*HWSZ + (gy0+ty)*WW + gx0+tx] = md;

    float wmin = md, wmax = md;
    #pragma unroll
    for (int o=16;o>0;o>>=1){
        wmin = fminf(wmin, __shfl_xor_sync(0xffffffffu, wmin, o));
        wmax = fmaxf(wmax, __shfl_xor_sync(0xffffffffu, wmax, o));
    }
    int wd = tid >> 5, ld = tid & 31;
    if (ld == 0){ smin[wd] = wmin; smax[wd] = wmax; }

    // ---- L2 prefetch of this CTA's x tile (overlaps barrier skew) ----
    const float* xbase = x + (size_t)b*CIN*HWSZ;
    {
        const float* p0 = xbase + gy0*WW + gx0;
        for (int i = tid; i < 2048; i += 256){
            int c = i >> 3, r = i & 7;
            const float* p = p0 + (size_t)c*HWSZ + r*WW;
            asm volatile("prefetch.global.L2 [%0];" :: "l"(p));
        }
    }

    // EVERY thread fences its own g_mind store device-wide before the arrive.
    __threadfence();
    __syncthreads();

    // ---------- grid-wide barrier (release arrive / acquire spin) ----------
    if (tid == 0){
        float bm = smin[0], bM = smax[0];
        #pragma unroll
        for (int i=1;i<8;i++){ bm = fminf(bm, smin[i]); bM = fmaxf(bM, smax[i]); }
        atomicMin(&g_minbits[b], __float_as_uint(bm));
        atomicMax(&g_maxbits[b], __float_as_uint(bM));
        __threadfence();
        bar_arrive_release(&g_bar);
        while (ld_acquire(&g_bar) < (unsigned)NCTA234) { }
        sminmax[0] = __uint_as_float(ldcg_u32(&g_minbits[b]));
        sminmax[1] = __uint_as_float(ldcg_u32(&g_maxbits[b]));
    }
    __syncthreads();

    // ---------- attention head ----------
    float dmin = sminmax[0];
    float inv  = 1.0f/(sminmax[1] - dmin + 1e-6f);
    const float* mdp = g_mind + b*HWSZ;

    for (int i = tid; i < 12*36; i += 256){
        int ly = i/36, lx = i%36;
        int yy = gy0 - 2 + ly, xx = gx0 - 2 + lx;
        float v = 0.f;
        if ((unsigned)yy < HH && (unsigned)xx < WW)
            v = (mdp[yy*WW + xx] - dmin) * inv;
        sdev[i] = v;
    }
    __syncthreads();

    int cy = ty + 2, cx = tx + 2;
    float t1 = 0.f;
    #pragma unroll
    for (int dy=0;dy<3;dy++)
        #pragma unroll
        for (int dx=0;dx<3;dx++)
            t1 = fmaf(bs_dw[dy*3+dx], sdev[(cy+dy-1)*36 + cx+dx-1], t1);
    { float g=bs_bn1[0], be=bs_bn1[1], mm=bs_bn1[2], v=bs_bn1[3];
      float sc = g*rsqrtf(v+BN_EPS); t1 = siluf_(fmaf(t1, sc, be - mm*sc)); }
    float t2 = 0.f;
    #pragma unroll
    for (int dy=0;dy<5;dy++)
        #pragma unroll
        for (int dx=0;dx<5;dx++)
            t2 = fmaf(bl_dw[dy*5+dx], sdev[(cy+dy-2)*36 + cx+dx-2], t2);
    { float g=bl_bn1[0], be=bl_bn1[1], mm=bl_bn1[2], v=bl_bn1[3];
      float sc = g*rsqrtf(v+BN_EPS); t2 = siluf_(fmaf(t2, sc, be - mm*sc)); }

    float logit = fuse_b[0];
    #pragma unroll
    for (int c=0;c<8;c++){
        float g=bs_bn2[c], be=bs_bn2[8+c], mm=bs_bn2[16+c], v=bs_bn2[24+c];
        float sc = g*rsqrtf(v+BN_EPS);
        float f1 = siluf_(fmaf(bs_pw[c]*t1, sc, be - mm*sc));
        logit = fmaf(fuse_w[c], f1, logit);
    }
    #pragma unroll
    for (int c=0;c<8;c++){
        float g=bl_bn2[c], be=bl_bn2[8+c], mm=bl_bn2[16+c], v=bl_bn2[24+c];
        float sc = g*rsqrtf(v+BN_EPS);
        float f2 = siluf_(fmaf(bl_pw[c]*t2, sc, be - mm*sc));
        logit = fmaf(fuse_w[8+c], f2, logit);
    }
    float fac = 1.0f + gamma[0]*sigmoidf_(logit);

    // ---------- fused apply: out = x * fac over all 256 channels ----------
    {
        int px = (gy0+ty)*WW + gx0 + tx;
        const float* xp = xbase + px;
        float* op = out + (size_t)b*CIN*HWSZ + px;
        #pragma unroll 4
        for (int c = 0; c < CIN; c += 4){
            float v0 = xp[(size_t)(c  )*HWSZ];
            float v1 = xp[(size_t)(c+1)*HWSZ];
            float v2 = xp[(size_t)(c+2)*HWSZ];
            float v3 = xp[(size_t)(c+3)*HWSZ];
            op[(size_t)(c  )*HWSZ] = v0*fac;
            op[(size_t)(c+1)*HWSZ] = v1*fac;
            op[(size_t)(c+2)*HWSZ] = v2*fac;
            op[(size_t)(c+3)*HWSZ] = v3*fac;
        }
    }
}

// ---------------------------------------------------------------- launch
extern "C" void kernel_launch(void* const* d_in, const int* in_sizes, int n_in,
                              void* d_out, int out_size){
    const float* x      = (const float*)d_in[0];
    const float* fp_w1  = (const float*)d_in[1];
    const float* fp_bn1 = (const float*)d_in[2];
    const float* fp_dw  = (const float*)d_in[3];
    const float* fp_bn2 = (const float*)d_in[4];
    const float* protos = (const float*)d_in[5];
    const float* bs_dw  = (const float*)d_in[6];
    const float* bs_bn1 = (const float*)d_in[7];
    const float* bs_pw  = (const float*)d_in[8];
    const float* bs_bn2 = (const float*)d_in[9];
    const float* bl_dw  = (const float*)d_in[10];
    const float* bl_bn1 = (const float*)d_in[11];
    const float* bl_pw  = (const float*)d_in[12];
    const float* bl_bn2 = (const float*)d_in[13];
    const float* fuse_w = (const float*)d_in[14];
    const float* fuse_b = (const float*)d_in[15];
    const float* gamma  = (const float*)d_in[16];
    float* out = (float*)d_out;

    cudaFuncSetAttribute(k1_mma, cudaFuncAttributeMaxDynamicSharedMemorySize, SM_TOTAL);
    cudaFuncSetAttribute(k234,   cudaFuncAttributeMaxDynamicSharedMemorySize, K234_SMEM);
    k1_mma<<<dim3(64, BB), 256, SM_TOTAL>>>(x, fp_w1, fp_bn1);
    k234<<<dim3(4, 16, BB), dim3(32, 8), K234_SMEM>>>(fp_dw, fp_bn2, protos,
                                           bs_dw, bs_bn1, bs_pw, bs_bn2,
                                           bl_dw, bl_bn1, bl_pw, bl_bn2,
                                           fuse_w, fuse_b, gamma, x, out);
}

// round 12
// speedup vs baseline: 1.3085x; 1.3085x over previous
#include <cuda_runtime.h>
#include <cstdint>
#include <math.h>

#define BB 4
#define CIN 256
#define PP 64
#define HH 128
#define WW 128
#define HWSZ (HH*WW)
#define KK 8
#define BN_EPS 1e-5f
#define NCTA234 (4*16*BB)

// Scratch (device globals: allocation-free)
__device__ float g_h[BB*PP*HWSZ];      // after 1x1 conv + BN + SiLU
__device__ float g_mind[BB*HWSZ];      // per-pixel min distance / (tau+1e-6)
__device__ float g_factor[BB*HWSZ];    // 1 + gamma*attn
__device__ unsigned int g_minbits[BB];
__device__ unsigned int g_maxbits[BB];
__device__ unsigned int g_bar;

__device__ __forceinline__ float sigmoidf_(float x){ return 1.0f/(1.0f+__expf(-x)); }
__device__ __forceinline__ float siluf_(float x){ return x*sigmoidf_(x); }

__device__ __forceinline__ uint32_t smem_u32(const void* p){
    uint32_t a;
    asm("{ .reg .u64 t; cvta.to.shared.u64 t, %1; cvt.u32.u64 %0, t; }" : "=r"(a) : "l"(p));
    return a;
}
__device__ __forceinline__ uint32_t pack_bf16x2(float x0, float x1){
    uint32_t r;
    asm("cvt.rn.bf16x2.f32 %0, %1, %2;" : "=r"(r) : "f"(x1), "f"(x0));
    return r;
}
__device__ __forceinline__ void ldsm_x4(uint32_t* r, uint32_t addr){
    asm volatile("ldmatrix.sync.aligned.m8n8.x4.shared.b16 {%0,%1,%2,%3}, [%4];"
        : "=r"(r[0]),"=r"(r[1]),"=r"(r[2]),"=r"(r[3]) : "r"(addr));
}
__device__ __forceinline__ void ldsm_x2(uint32_t& r0, uint32_t& r1, uint32_t addr){
    asm volatile("ldmatrix.sync.aligned.m8n8.x2.shared.b16 {%0,%1}, [%2];"
        : "=r"(r0),"=r"(r1) : "r"(addr));
}
__device__ __forceinline__ void mma_bf16(float* d, const uint32_t* a, uint32_t b0, uint32_t b1){
    asm volatile("mma.sync.aligned.m16n8k16.row.col.f32.bf16.bf16.f32 "
        "{%0,%1,%2,%3},{%4,%5,%6,%7},{%8,%9},{%0,%1,%2,%3};"
        : "+f"(d[0]),"+f"(d[1]),"+f"(d[2]),"+f"(d[3])
        : "r"(a[0]),"r"(a[1]),"r"(a[2]),"r"(a[3]),"r"(b0),"r"(b1));
}
__device__ __forceinline__ uint32_t ldcg_u32(const unsigned int* p){
    uint32_t v;
    asm volatile("ld.global.cg.u32 %0, [%1];" : "=r"(v) : "l"(p));
    return v;
}
__device__ __forceinline__ void bar_arrive_release(unsigned int* p){
    uint32_t old;
    asm volatile("atom.global.release.gpu.add.u32 %0, [%1], 1;" : "=r"(old) : "l"(p) : "memory");
}
__device__ __forceinline__ uint32_t ld_acquire(const unsigned int* p){
    uint32_t v;
    asm volatile("ld.global.acquire.gpu.u32 %0, [%1];" : "=r"(v) : "l"(p) : "memory");
    return v;
}

// ---------------- k1 SMEM layout ----------------
#define APITCH 36                          // u32 pitch for A (144B)
#define BPITCH 132                         // u32 pitch for B (528B), full K
#define SM_SC    0
#define SM_SH    256
#define ABYTES   (128*APITCH*4)            // 18432
#define SM_A0    512
#define SM_B     (SM_A0 + 2*ABYTES)        // 37376
#define SM_TOTAL (SM_B + 64*BPITCH*4)      // 71168

// stage 32 x-floats (one K=64 chunk of A) into registers
static __device__ __forceinline__ void a_stage(const float* __restrict__ xp,
                                               int kn, float* xa, int tid){
    int kg0 = tid >> 7;                    // 0 or 1
    #pragma unroll
    for (int it = 0; it < 4; it++){
        int kbase = kn*64 + (kg0 + it*2)*8;
        #pragma unroll
        for (int t = 0; t < 4; t++){
            xa[it*8 + 2*t]     = xp[(size_t)(kbase + 2*t    )*HWSZ];
            xa[it*8 + 2*t + 1] = xp[(size_t)(kbase + 2*t + 1)*HWSZ];
        }
    }
}
// cvt staged regs -> bf16x2, STS.128 into buffer
static __device__ __forceinline__ void a_commit(const float* xa, uint32_t* a_buf, int tid){
    int px  = tid & 127;
    int kg0 = tid >> 7;
    #pragma unroll
    for (int it = 0; it < 4; it++){
        int kg = kg0 + it*2;
        uint32_t hi[4];
        #pragma unroll
        for (int t = 0; t < 4; t++)
            hi[t] = pack_bf16x2(xa[it*8 + 2*t], xa[it*8 + 2*t + 1]);
        *(uint4*)(a_buf + px*APITCH + kg*4) = make_uint4(hi[0],hi[1],hi[2],hi[3]);
    }
}

// ---------------------------------------------------------------- k1: 1x1 conv, bf16 HMMA
// 2 pixel-blocks per CTA, B converted once (full K), register-staged A pipeline.
__global__ __launch_bounds__(256, 2)
void k1_mma(const float* __restrict__ x, const float* __restrict__ w,
            const float* __restrict__ bn){
    extern __shared__ char smem[];
    uint32_t sb = smem_u32(smem);
    float* ssc = (float*)(smem + SM_SC);
    float* ssh = (float*)(smem + SM_SH);
    uint32_t* b_buf = (uint32_t*)(smem + SM_B);

    int b    = blockIdx.y;
    int pix0 = blockIdx.x * 256;
    int tid  = threadIdx.x;
    int wid  = tid >> 5;
    int lane = tid & 31;
    int gid  = lane >> 2, tig = lane & 3;
    int pw   = (wid >> 1) * 32;
    int n0w  = (wid & 1) * 32;

    if (blockIdx.x == 0 && blockIdx.y == 0 && tid < BB + 1){
        if (tid < BB){ g_minbits[tid] = 0x7F7FFFFFu; g_maxbits[tid] = 0u; }
        else g_bar = 0u;
    }
    if (tid < PP){
        float g = bn[tid], be = bn[PP+tid], m = bn[2*PP+tid], v = bn[3*PP+tid];
        float sc = g * rsqrtf(v + BN_EPS);
        ssc[tid] = sc; ssh[tid] = be - m*sc;
    }

    // ---- convert B once: 64 couts x 256 K -> bf16x2 [co][kpair], pitch 132 u32 ----
    {
        int co = tid & 63;
        int kq = (tid >> 6) * 64;            // k-float base: 0,64,128,192
        const float* wp = w + co*CIN + kq;
        #pragma unroll
        for (int t = 0; t < 8; t++){
            float4 w0 = *(const float4*)(wp + t*8);
            float4 w1 = *(const float4*)(wp + t*8 + 4);
            uint32_t hi[4];
            hi[0] = pack_bf16x2(w0.x, w0.y);
            hi[1] = pack_bf16x2(w0.z, w0.w);
            hi[2] = pack_bf16x2(w1.x, w1.y);
            hi[3] = pack_bf16x2(w1.z, w1.w);
            *(uint4*)(b_buf + co*BPITCH + kq/2 + t*4) = make_uint4(hi[0],hi[1],hi[2],hi[3]);
        }
    }

    uint32_t a_row = (uint32_t)(lane & 15);
    uint32_t a_kof = (uint32_t)(lane >> 4) * 16;
    uint32_t b_row = (uint32_t)(lane & 7);
    uint32_t b_kof = (uint32_t)((lane >> 3) & 1) * 16;

    float xa[32];

    #pragma unroll 1
    for (int pb = 0; pb < 2; pb++){
        const float* xp = x + (size_t)b*CIN*HWSZ + pix0 + pb*128 + (tid & 127);

        float acc[2][4][4];
        #pragma unroll
        for (int mt=0;mt<2;mt++)
            #pragma unroll
            for (int j=0;j<4;j++)
                #pragma unroll
                for (int i=0;i<4;i++) acc[mt][j][i] = 0.f;

        // prologue: chunk 0
        a_stage(xp, 0, xa, tid);
        a_commit(xa, (uint32_t*)(smem + SM_A0), tid);
        __syncthreads();

        #pragma unroll 1
        for (int c = 0; c < 4; c++){
            uint32_t curA = sb + SM_A0 + (uint32_t)(c & 1) * ABYTES;
            // 1) issue next chunk's loads (independent -> in flight during MMA)
            if (c < 3) a_stage(xp, c+1, xa, tid);
            // 2) MMA on current buffer: 4 k16 steps
            #pragma unroll
            for (int ks = 0; ks < 4; ks++){
                uint32_t kbyteA = (uint32_t)ks * 32;
                uint32_t kbyteB = (uint32_t)c * 128 + (uint32_t)ks * 32;
                uint32_t ah[2][4];
                #pragma unroll
                for (int mt=0;mt<2;mt++){
                    uint32_t ra = (pw + mt*16 + a_row) * (APITCH*4) + kbyteA + a_kof;
                    ldsm_x4(ah[mt], curA + ra);
                }
                #pragma unroll
                for (int j=0;j<4;j++){
                    uint32_t rb = (n0w + j*8 + b_row) * (BPITCH*4) + kbyteB + b_kof;
                    uint32_t bh0, bh1;
                    ldsm_x2(bh0, bh1, sb + SM_B + rb);
                    #pragma unroll
                    for (int mt=0;mt<2;mt++)
                        mma_bf16(acc[mt][j], ah[mt], bh0, bh1);
                }
            }
            // 3) consume the staged loads (latency hidden by MMA)
            if (c < 3) a_commit(xa, (uint32_t*)(smem + SM_A0 + ((c+1) & 1) * ABYTES), tid);
            __syncthreads();
        }

        // epilogue: BN + SiLU, store
        #pragma unroll
        for (int mt=0;mt<2;mt++){
            int pix = pix0 + pb*128 + pw + mt*16 + gid;
            #pragma unroll
            for (int j=0;j<4;j++){
                int cc = n0w + j*8 + tig*2;
                float sc0 = ssc[cc],   sh0 = ssh[cc];
                float sc1 = ssc[cc+1], sh1 = ssh[cc+1];
                float* h0 = g_h + (size_t)(b*PP + cc)*HWSZ;
                float* h1 = h0 + HWSZ;
                h0[pix]   = siluf_(fmaf(acc[mt][j][0], sc0, sh0));
                h1[pix]   = siluf_(fmaf(acc[mt][j][1], sc1, sh1));
                h0[pix+8] = siluf_(fmaf(acc[mt][j][2], sc0, sh0));
                h1[pix+8] = siluf_(fmaf(acc[mt][j][3], sc1, sh1));
            }
        }
    }
}

// ---------------- k234 dynamic smem layout (float offsets) ----------------
#define K234_FLOATS 23440
#define K234_SMEM   (K234_FLOATS*4)

// ---------------------------------------------------------------- k234: dw3x3+dist -> grid barrier -> attention -> factor
__global__ __launch_bounds__(256) void k234(
        const float* __restrict__ dw, const float* __restrict__ bn,
        const float* __restrict__ protos,
        const float* __restrict__ bs_dw, const float* __restrict__ bs_bn1,
        const float* __restrict__ bs_pw, const float* __restrict__ bs_bn2,
        const float* __restrict__ bl_dw, const float* __restrict__ bl_bn1,
        const float* __restrict__ bl_pw, const float* __restrict__ bl_bn2,
        const float* __restrict__ fuse_w, const float* __restrict__ fuse_b,
        const float* __restrict__ gamma){
    extern __shared__ float sm[];
    float* tile = sm;                 // [c][r][col] = c*340 + r*34 + col
    float* ps   = sm + 21760;
    float* sdw  = sm + 22272;
    float* ssc  = sm + 22848;
    float* ssh  = sm + 22912;
    float* pn   = sm + 22976;
    float* smin = sm + 22984;
    float* smax = sm + 22992;
    float* sdev = sm + 23000;         // [ly][lx] = ly*36 + lx
    float* sminmax = sm + 23432;

    int b   = blockIdx.z;
    int gx0 = blockIdx.x*32, gy0 = blockIdx.y*8;
    int tx  = threadIdx.x,  ty  = threadIdx.y;
    int tid = ty*32 + tx;

    for (int i = tid; i < KK*PP; i += 256) ps[i] = protos[i];
    for (int i = tid; i < PP*9;  i += 256) sdw[i] = dw[i];
    if (tid < PP){
        float g=bn[tid], be=bn[PP+tid], m=bn[2*PP+tid], v=bn[3*PP+tid];
        float sc = g*rsqrtf(v+BN_EPS);
        ssc[tid] = sc; ssh[tid] = be - m*sc;
    }
    if (tid < KK){
        float s = 0.f;
        #pragma unroll
        for (int c=0;c<PP;c++){ float p = protos[tid*PP+c]; s = fmaf(p,p,s); }
        pn[tid] = s;
    }

    // ---- single-pass halo tile load: all 64 channels ----
    const float* hb = g_h + (size_t)b*PP*HWSZ;
    for (int i = tid; i < 64*340; i += 256){
        int c   = i / 340;
        int rem = i - c*340;
        int r   = rem / 34;
        int col = rem - r*34;
        int yy = gy0 - 1 + r, xx = gx0 - 1 + col;
        float v = 0.f;
        if ((unsigned)yy < HH && (unsigned)xx < WW)
            v = hb[(size_t)c*HWSZ + yy*WW + xx];
        tile[i] = v;
    }
    __syncthreads();

    float nf = 0.f, dot[KK];
    #pragma unroll
    for (int k=0;k<KK;k++) dot[k] = 0.f;

    #pragma unroll 4
    for (int c = 0; c < PP; c++){
        const float* tc = tile + c*340 + ty*34 + tx;
        float s = 0.f;
        #pragma unroll
        for (int dy=0;dy<3;dy++)
            #pragma unroll
            for (int dx=0;dx<3;dx++)
                s = fmaf(sdw[c*9+dy*3+dx], tc[dy*34+dx], s);
        float pr = siluf_(fmaf(s, ssc[c], ssh[c]));
        nf = fmaf(pr, pr, nf);
        #pragma unroll
        for (int k=0;k<KK;k++) dot[k] = fmaf(pr, ps[k*PP+c], dot[k]);
    }

    float m = 3.4e38f;
    #pragma unroll
    for (int k=0;k<KK;k++) m = fminf(m, nf + pn[k] - 2.f*dot[k]);
    float md = sqrtf(fmaxf(m, 0.f)) * (1.0f/(1.0f + 1e-6f));
    g_mind[b*HWSZ + (gy0+ty)*WW + gx0+tx] = md;

    float wmin = md, wmax = md;
    #pragma unroll
    for (int o=16;o>0;o>>=1){
        wmin = fminf(wmin, __shfl_xor_sync(0xffffffffu, wmin, o));
        wmax = fmaxf(wmax, __shfl_xor_sync(0xffffffffu, wmax, o));
    }
    int wd = tid >> 5, ld = tid & 31;
    if (ld == 0){ smin[wd] = wmin; smax[wd] = wmax; }

    // EVERY thread fences its own g_mind store device-wide before the arrive.
    __threadfence();
    __syncthreads();

    // ---------- grid-wide barrier (release arrive / acquire spin) ----------
    if (tid == 0){
        float bm = smin[0], bM = smax[0];
        #pragma unroll
        for (int i=1;i<8;i++){ bm = fminf(bm, smin[i]); bM = fmaxf(bM, smax[i]); }
        atomicMin(&g_minbits[b], __float_as_uint(bm));
        atomicMax(&g_maxbits[b], __float_as_uint(bM));
        __threadfence();
        bar_arrive_release(&g_bar);
        while (ld_acquire(&g_bar) < (unsigned)NCTA234) { }
        sminmax[0] = __uint_as_float(ldcg_u32(&g_minbits[b]));
        sminmax[1] = __uint_as_float(ldcg_u32(&g_maxbits[b]));
    }
    __syncthreads();

    // ---------- attention head ----------
    float dmin = sminmax[0];
    float inv  = 1.0f/(sminmax[1] - dmin + 1e-6f);
    const float* mdp = g_mind + b*HWSZ;

    for (int i = tid; i < 12*36; i += 256){
        int ly = i/36, lx = i%36;
        int yy = gy0 - 2 + ly, xx = gx0 - 2 + lx;
        float v = 0.f;
        if ((unsigned)yy < HH && (unsigned)xx < WW)
            v = (mdp[yy*WW + xx] - dmin) * inv;
        sdev[i] = v;
    }
    __syncthreads();

    int cy = ty + 2, cx = tx + 2;
    float t1 = 0.f;
    #pragma unroll
    for (int dy=0;dy<3;dy++)
        #pragma unroll
        for (int dx=0;dx<3;dx++)
            t1 = fmaf(bs_dw[dy*3+dx], sdev[(cy+dy-1)*36 + cx+dx-1], t1);
    { float g=bs_bn1[0], be=bs_bn1[1], mm=bs_bn1[2], v=bs_bn1[3];
      float sc = g*rsqrtf(v+BN_EPS); t1 = siluf_(fmaf(t1, sc, be - mm*sc)); }
    float t2 = 0.f;
    #pragma unroll
    for (int dy=0;dy<5;dy++)
        #pragma unroll
        for (int dx=0;dx<5;dx++)
            t2 = fmaf(bl_dw[dy*5+dx], sdev[(cy+dy-2)*36 + cx+dx-2], t2);
    { float g=bl_bn1[0], be=bl_bn1[1], mm=bl_bn1[2], v=bl_bn1[3];
      float sc = g*rsqrtf(v+BN_EPS); t2 = siluf_(fmaf(t2, sc, be - mm*sc)); }

    float logit = fuse_b[0];
    #pragma unroll
    for (int c=0;c<8;c++){
        float g=bs_bn2[c], be=bs_bn2[8+c], mm=bs_bn2[16+c], v=bs_bn2[24+c];
        float sc = g*rsqrtf(v+BN_EPS);
        float f1 = siluf_(fmaf(bs_pw[c]*t1, sc, be - mm*sc));
        logit = fmaf(fuse_w[c], f1, logit);
    }
    #pragma unroll
    for (int c=0;c<8;c++){
        float g=bl_bn2[c], be=bl_bn2[8+c], mm=bl_bn2[16+c], v=bl_bn2[24+c];
        float sc = g*rsqrtf(v+BN_EPS);
        float f2 = siluf_(fmaf(bl_pw[c]*t2, sc, be - mm*sc));
        logit = fmaf(fuse_w[8+c], f2, logit);
    }
    g_factor[b*HWSZ + (gy0+ty)*WW + gx0+tx] = 1.0f + gamma[0]*sigmoidf_(logit);
}

// ---------------------------------------------------------------- k5: out = x * factor, 8 floats/thread
__global__ __launch_bounds__(256) void k5_apply(const float* __restrict__ x,
                                                float* __restrict__ out){
    size_t i = ((size_t)blockIdx.x*256 + threadIdx.x) * 8;   // 8-float slab, never crosses HWSZ
    float4 x0 = *(const float4*)(x + i);
    float4 x1 = *(const float4*)(x + i + 4);
    size_t pos = i & (size_t)(HWSZ - 1);
    int b      = (int)(i >> 22);
    const float* fb = g_factor + (size_t)b*HWSZ + pos;
    float4 f0 = *(const float4*)fb;
    float4 f1 = *(const float4*)(fb + 4);
    float4 o0, o1;
    o0.x = x0.x*f0.x; o0.y = x0.y*f0.y; o0.z = x0.z*f0.z; o0.w = x0.w*f0.w;
    o1.x = x1.x*f1.x; o1.y = x1.y*f1.y; o1.z = x1.z*f1.z; o1.w = x1.w*f1.w;
    *(float4*)(out + i)     = o0;
    *(float4*)(out + i + 4) = o1;
}

// ---------------------------------------------------------------- launch
extern "C" void kernel_launch(void* const* d_in, const int* in_sizes, int n_in,
                              void* d_out, int out_size){
    const float* x      = (const float*)d_in[0];
    const float* fp_w1  = (const float*)d_in[1];
    const float* fp_bn1 = (const float*)d_in[2];
    const float* fp_dw  = (const float*)d_in[3];
    const float* fp_bn2 = (const float*)d_in[4];
    const float* protos = (const float*)d_in[5];
    const float* bs_dw  = (const float*)d_in[6];
    const float* bs_bn1 = (const float*)d_in[7];
    const float* bs_pw  = (const float*)d_in[8];
    const float* bs_bn2 = (const float*)d_in[9];
    const float* bl_dw  = (const float*)d_in[10];
    const float* bl_bn1 = (const float*)d_in[11];
    const float* bl_pw  = (const float*)d_in[12];
    const float* bl_bn2 = (const float*)d_in[13];
    const float* fuse_w = (const float*)d_in[14];
    const float* fuse_b = (const float*)d_in[15];
    const float* gamma  = (const float*)d_in[16];
    float* out = (float*)d_out;

    cudaFuncSetAttribute(k1_mma, cudaFuncAttributeMaxDynamicSharedMemorySize, SM_TOTAL);
    cudaFuncSetAttribute(k234,   cudaFuncAttributeMaxDynamicSharedMemorySize, K234_SMEM);
    k1_mma<<<dim3(64, BB), 256, SM_TOTAL>>>(x, fp_w1, fp_bn1);
    k234<<<dim3(4, 16, BB), dim3(32, 8), K234_SMEM>>>(fp_dw, fp_bn2, protos,
                                           bs_dw, bs_bn1, bs_pw, bs_bn2,
                                           bl_dw, bl_bn1, bl_pw, bl_bn2,
                                           fuse_w, fuse_b, gamma);
    k5_apply<<<(BB*CIN*HWSZ)/8/256, 256>>>(x, out);
}